// round 8
// baseline (speedup 1.0000x reference)
#include <cuda_runtime.h>
#include <math.h>

#define BB 4
#define HH 544
#define WW 960
#define H2 272
#define W2 480
#define MD 24
#define TILE_BLOCKS 4080

// ---------------- scratch (no allocations allowed) ----------------
__device__ float g_lg[BB * H2 * W2];
__device__ float g_rg[BB * H2 * W2];
__device__ float g_nd[BB * H2 * W2];
__device__ float g_nc[BB * H2 * W2];
// accumulators padded to one 128B line each to avoid LTS atomic serialization
// idx: 0 gtNum 1 gtDen 2 photoNum 3 photoDen 4 signSum 5 magSum 6 activeSum 7 smx 8 smy
__device__ double g_acc[9 * 16];
__device__ int g_counter;   // zero-initialized; self-resetting

// ---------------- helpers ----------------
__device__ __forceinline__ float blockReduceSum(float v, float* sbuf) {
    int tid = threadIdx.x + threadIdx.y * blockDim.x;
    int lane = tid & 31, wid = tid >> 5;
#pragma unroll
    for (int o = 16; o > 0; o >>= 1) v += __shfl_down_sync(0xffffffffu, v, o);
    if (lane == 0) sbuf[wid] = v;
    __syncthreads();
    int nw = (blockDim.x * blockDim.y + 31) >> 5;
    v = (tid < nw) ? sbuf[tid] : 0.f;
    if (wid == 0) {
#pragma unroll
        for (int o = 16; o > 0; o >>= 1) v += __shfl_down_sync(0xffffffffu, v, o);
    }
    __syncthreads();
    return v;  // valid at tid 0
}

// ---------------- kernels ----------------
// half-res grayscale + accumulator/counter zeroing (block 0)
__global__ void downsample_kernel(const float* __restrict__ left,
                                  const float* __restrict__ right) {
    if (blockIdx.x == 0) {
        if (threadIdx.x < 9 * 16) g_acc[threadIdx.x] = 0.0;
        if (threadIdx.x == 0) g_counter = 0;
    }
    int i = blockIdx.x * blockDim.x + threadIdx.x;
    const int NPAIR = W2 / 2;  // 240
    if (i >= BB * H2 * NPAIR) return;
    int px = i % NPAIR;
    int y = (i / NPAIR) % H2;
    int b = i / (NPAIR * H2);
    float l0 = 0.f, l1 = 0.f, r0 = 0.f, r1 = 0.f;
#pragma unroll
    for (int c = 0; c < 3; c++) {
        int base = ((b * 3 + c) * HH + 2 * y) * WW + 4 * px;
        float4 a0 = *(const float4*)(left + base);
        float4 a1 = *(const float4*)(left + base + WW);
        l0 += (a0.x + a0.y + a1.x + a1.y);
        l1 += (a0.z + a0.w + a1.z + a1.w);
        float4 b0 = *(const float4*)(right + base);
        float4 b1 = *(const float4*)(right + base + WW);
        r0 += (b0.x + b0.y + b1.x + b1.y);
        r1 += (b0.z + b0.w + b1.z + b1.w);
    }
    const float S = 0.25f / 3.0f;
    int o = (b * H2 + y) * W2 + 2 * px;
    *(float2*)(g_lg + o) = make_float2(l0 * S, l1 * S);
    *(float2*)(g_rg + o) = make_float2(r0 * S, r1 * S);
}

// NCC disparity search: one CTA per (b, QUAD of half-res rows), 480 threads
// (one per column). Rows 1..3 stats derived from row 0 by register rolling:
// S_k = S_{k-1} - lg[k-1]*v[k-1] + lg[k+10]*v[k+10]. 14 rgS loads serve all
// four vertical sums per (x,d).
__global__ void __launch_bounds__(480) ncc_kernel() {
    __shared__ float rgS[14][528];             // rows y0-5..y0+8, zero-padded +/-24
    __shared__ float crp[4][560], cr2p[4][560];// rg column sums per row (idx=x+40)
    __shared__ float Hcr[4][528], Hcr2[4][528];// 11-box of crp at u=idx-24
    __shared__ float ccS[4][6][496];           // cross column sums, idx = x+8
    float* clBase = &ccS[0][0][0];             // setup-only aliases: 8 arrays x 560
    const float NORM = 1.0f / 121.0f;

    int pr = blockIdx.x;
    int b = pr / (H2 / 4);
    int yq = pr - b * (H2 / 4);
    int y0 = 4 * yq;
    int x = threadIdx.x;
    const float* lgB = g_lg + b * H2 * W2;
    const float* rgB = g_rg + b * H2 * W2;

    float lgR[14];
    float cr[4], cr2[4], cl[4], cl2[4];
#pragma unroll
    for (int k = 0; k < 4; k++) { cr[k] = 0.f; cr2[k] = 0.f; cl[k] = 0.f; cl2[k] = 0.f; }
#pragma unroll
    for (int r = 0; r < 14; r++) {
        int yy = y0 + r - 5;
        float lv = 0.f, rv = 0.f;
        if (yy >= 0 && yy < H2) { lv = lgB[yy * W2 + x]; rv = rgB[yy * W2 + x]; }
        lgR[r] = lv;
        rgS[r][x + 24] = rv;
        if (x < 24) { rgS[r][x] = 0.f; rgS[r][x + 504] = 0.f; }
#pragma unroll
        for (int k = 0; k < 4; k++) {
            if (r >= k && r <= k + 10) {
                cr[k] += rv; cr2[k] += rv * rv;
                cl[k] += lv; cl2[k] += lv * lv;
            }
        }
    }
#pragma unroll
    for (int k = 0; k < 4; k++) {
        crp[k][x + 40] = cr[k];  cr2p[k][x + 40] = cr2[k];
        (clBase + (2 * k) * 560)[x + 40] = cl[k];
        (clBase + (2 * k + 1) * 560)[x + 40] = cl2[k];
    }
    if (x < 40) {
#pragma unroll
        for (int k = 0; k < 4; k++) {
            crp[k][x] = 0.f; cr2p[k][x] = 0.f;
            (clBase + (2 * k) * 560)[x] = 0.f; (clBase + (2 * k + 1) * 560)[x] = 0.f;
        }
    }
    if (x >= 440) {
#pragma unroll
        for (int k = 0; k < 4; k++) {
            crp[k][x + 80] = 0.f; cr2p[k][x + 80] = 0.f;
            (clBase + (2 * k) * 560)[x + 80] = 0.f; (clBase + (2 * k + 1) * 560)[x + 80] = 0.f;
        }
    }
    __syncthreads();

    // Hcr[k][i] = 11-box of crp[k] centered at col i-24 : taps crp[k][i+11..i+21]
    for (int i = x; i < 528; i += 480) {
#pragma unroll
        for (int k = 0; k < 4; k++) {
            float s = 0.f, s2 = 0.f;
#pragma unroll
            for (int t = 0; t < 11; t++) { s += crp[k][i + 11 + t]; s2 += cr2p[k][i + 11 + t]; }
            Hcr[k][i] = s; Hcr2[k][i] = s2;
        }
    }
    // left stats for all four rows
    float lm[4], ls[4];
#pragma unroll
    for (int k = 0; k < 4; k++) {
        const float* cp = clBase + (2 * k) * 560;
        const float* c2 = clBase + (2 * k + 1) * 560;
        float m = 0.f, q = 0.f;
#pragma unroll
        for (int t = 0; t < 11; t++) { m += cp[x + 35 + t]; q += c2[x + 35 + t]; }
        m *= NORM; q *= NORM;
        lm[k] = m;
        ls[k] = sqrtf(fmaxf(q - m * m, 1e-8f));
    }
    __syncthreads();   // clBase reads done; ccS region now free

    // zero ccS pads (idx 0..7, 488..495)
    if (x < 8) {
#pragma unroll
        for (int k = 0; k < 4; k++)
#pragma unroll
            for (int j = 0; j < 6; j++) { ccS[k][j][x] = 0.f; ccS[k][j][488 + x] = 0.f; }
    }

    float bestC[4], bestD[4];
#pragma unroll
    for (int k = 0; k < 4; k++) { bestC[k] = -1.f; bestD[k] = 0.f; }
    bool interior = (x >= 5 && x < 475);

    for (int g = 0; g < 8; g++) {
        float ccr[4][6];
#pragma unroll
        for (int j = 0; j < 6; j++) {
            int idx = g * 6 + j;
            int d = (idx < 24) ? (idx - 24) : (idx - 23);
            int u = x + d + 24;
            float v0 = rgS[0][u], v1 = rgS[1][u], v2 = rgS[2][u];
            float v11 = rgS[11][u], v12 = rgS[12][u], v13 = rgS[13][u];
            float s = lgR[0] * v0 + lgR[1] * v1 + lgR[2] * v2;
#pragma unroll
            for (int r = 3; r < 11; r++) s += lgR[r] * rgS[r][u];
            float s1 = s - lgR[0] * v0 + lgR[11] * v11;
            float s2 = s1 - lgR[1] * v1 + lgR[12] * v12;
            float s3 = s2 - lgR[2] * v2 + lgR[13] * v13;
            ccr[0][j] = s;  ccS[0][j][x + 8] = s;
            ccr[1][j] = s1; ccS[1][j][x + 8] = s1;
            ccr[2][j] = s2; ccS[2][j][x + 8] = s2;
            ccr[3][j] = s3; ccS[3][j][x + 8] = s3;
        }
        __syncthreads();
#pragma unroll
        for (int j = 0; j < 6; j++) {
            int idx = g * 6 + j;
            int d = (idx < 24) ? (idx - 24) : (idx - 23);
            int u = x + d + 24;
#pragma unroll
            for (int k = 0; k < 4; k++) {
                // cross box: own column kept in register (10 taps)
                float cross = ccr[k][j];
#pragma unroll
                for (int t = -5; t < 0; t++) cross += ccS[k][j][x + 8 + t];
#pragma unroll
                for (int t = 1; t <= 5; t++) cross += ccS[k][j][x + 8 + t];
                float rm121, r2121;
                if (interior) {
                    rm121 = Hcr[k][u]; r2121 = Hcr2[k][u];
                } else {
                    rm121 = 0.f; r2121 = 0.f;
#pragma unroll
                    for (int t = -5; t <= 5; t++) {
                        int uu = x + t;
                        if (uu >= 0 && uu < W2) {
                            rm121 += crp[k][uu + d + 40];
                            r2121 += cr2p[k][uu + d + 40];
                        }
                    }
                }
                float rm = rm121 * NORM;
                float rstd = sqrtf(fmaxf(r2121 * NORM - rm * rm, 1e-8f));
                float ncc = (cross * NORM - lm[k] * rm) / (ls[k] * rstd + 1e-8f);
                if (ncc > bestC[k]) { bestC[k] = ncc; bestD[k] = (float)d; }
            }
        }
        __syncthreads();
    }
    int o = (b * H2 + y0) * W2 + x;
#pragma unroll
    for (int k = 0; k < 4; k++) {
        g_nd[o + k * W2] = bestD[k] * 2.0f;
        g_nc[o + k * W2] = fmaxf(bestC[k], 0.f);
    }
}

// ONE fused full-res pass: warp-on-the-fly + SSIM/L1 photometric + GT anchor
// + smoothness + sign/magnitude. 64x8 tiles, 128 threads, 4 outputs/thread.
// Last block folds the finalize step.
__global__ __launch_bounds__(128) void tile_kernel(const float* __restrict__ pred,
                                                   const float* __restrict__ gt,
                                                   const float* __restrict__ conf,
                                                   const float* __restrict__ occ,
                                                   const float* __restrict__ left,
                                                   const float* __restrict__ right,
                                                   float* __restrict__ out) {
    __shared__ float lS[3][10][66];
    __shared__ float wS[3][10][66];
    __shared__ float dS[10][66];
    __shared__ float sbuf[8];
    __shared__ int lastFlag;
    int b = blockIdx.z;
    int tx0 = blockIdx.x * 64, ty0 = blockIdx.y * 8;
    int tid = threadIdx.y * 16 + threadIdx.x;

    // halo load: compute warped right on the fly
    for (int i = tid; i < 10 * 66; i += 128) {
        int col = i % 66;
        int rrow = i / 66;
        int gx = tx0 + col - 1, gy = ty0 + rrow - 1;
        if (gx >= 0 && gx < WW && gy >= 0 && gy < HH) {
            float disp = pred[(b * HH + gy) * WW + gx];
            dS[rrow][col] = disp;
            float xs = (float)gx - disp;
            float xc = fminf(fmaxf(xs, 0.f), (float)(WW - 1));
            float x0f = floorf(xc);
            float w = xc - x0f;
            int x0i = (int)x0f;
            int x1i = min(x0i + 1, WW - 1);
#pragma unroll
            for (int c = 0; c < 3; c++) {
                const float* R = right + ((b * 3 + c) * HH + gy) * WW;
                wS[c][rrow][col] = R[x0i] * (1.f - w) + R[x1i] * w;
                lS[c][rrow][col] = left[((b * 3 + c) * HH + gy) * WW + gx];
            }
        } else {
            dS[rrow][col] = 0.f;
#pragma unroll
            for (int c = 0; c < 3; c++) { wS[c][rrow][col] = 0.f; lS[c][rrow][col] = 0.f; }
        }
    }
    __syncthreads();

    int tx = threadIdx.x, ty = threadIdx.y;
    int lx0 = 4 * tx;                 // local col of first output
    int gx0 = tx0 + lx0, gy = ty0 + ty;

    float ssAcc[4] = {0, 0, 0, 0}, l1Acc[4] = {0, 0, 0, 0};
    float sidx[4] = {0, 0, 0, 0}, sidy[4] = {0, 0, 0, 0};
    const float N9 = 1.f / 9.f;
    const float C1 = 1e-4f, C2 = 9e-4f;
#pragma unroll
    for (int c = 0; c < 3; c++) {
        float win[4][5];
#pragma unroll
        for (int j = 0; j < 4; j++)
#pragma unroll
            for (int q = 0; q < 5; q++) win[j][q] = 0.f;
        float prev1 = 0.f;
#pragma unroll
        for (int u = 0; u < 6; u++) {
            float l0 = lS[c][ty][lx0 + u], l1 = lS[c][ty + 1][lx0 + u], l2 = lS[c][ty + 2][lx0 + u];
            float m0 = wS[c][ty][lx0 + u], m1 = wS[c][ty + 1][lx0 + u], m2 = wS[c][ty + 2][lx0 + u];
            float cA = l0 + l1 + l2;
            float cB = m0 + m1 + m2;
            float cC = l0 * l0 + l1 * l1 + l2 * l2;
            float cD = m0 * m0 + m1 * m1 + m2 * m2;
            float cE = l0 * m0 + l1 * m1 + l2 * m2;
#pragma unroll
            for (int j = 0; j < 4; j++) {
                if (u >= j && u <= j + 2) {
                    win[j][0] += cA; win[j][1] += cB; win[j][2] += cC;
                    win[j][3] += cD; win[j][4] += cE;
                }
            }
            if (u >= 1 && u <= 4) {
                l1Acc[u - 1] += fabsf(l1 - m1);
                sidy[u - 1] += fabsf(l2 - l1);
            }
            if (u >= 2) sidx[u - 2] += fabsf(l1 - prev1);
            prev1 = l1;
        }
#pragma unroll
        for (int j = 0; j < 4; j++) {
            float mx = win[j][0] * N9, my = win[j][1] * N9;
            float vx = fmaxf(win[j][2] * N9 - mx * mx, 0.f);
            float vy = fmaxf(win[j][3] * N9 - my * my, 0.f);
            float cxy = win[j][4] * N9 - mx * my;
            float nn = (2.f * mx * my + C1) * (2.f * cxy + C2);
            float dd = (mx * mx + my * my + C1) * (vx + vy + C2);
            ssAcc[j] += fminf(fmaxf((1.f - nn / dd) * 0.5f, 0.f), 1.f);
        }
    }

    // per-output remaining terms
    int gi0 = (b * HH + gy) * WW + gx0;
    float4 gtv = *(const float4*)(gt + gi0);
    float4 cfv = *(const float4*)(conf + gi0);
    float4 ocv = *(const float4*)(occ + gi0);
    float gtA[4] = {gtv.x, gtv.y, gtv.z, gtv.w};
    float cfA[4] = {cfv.x, cfv.y, cfv.z, cfv.w};
    float ocA[4] = {ocv.x, ocv.y, ocv.z, ocv.w};
    int hid0 = (b * H2 + (gy >> 1)) * W2 + (gx0 >> 1);
    float ncP[2] = {g_nc[hid0], g_nc[hid0 + 1]};
    float ndP[2] = {g_nd[hid0], g_nd[hid0 + 1]};

    float s_gtn = 0.f, s_trust = 0.f, s_perr = 0.f, s_valid = 0.f;
    float s_sign = 0.f, s_mag = 0.f, s_act = 0.f, s_sx = 0.f, s_sy = 0.f;
#pragma unroll
    for (int j = 0; j < 4; j++) {
        int gx = gx0 + j;
        float dcen = dS[ty + 1][lx0 + j + 1];
        float xs = (float)gx - dcen;
        float valid = (xs > 0.f && xs < (float)(WW - 1)) ? 1.f : 0.f;
        float perr = (0.85f * (ssAcc[j] * (1.f / 3.f)) + 0.15f * (l1Acc[j] * (1.f / 3.f))) * valid;
        s_perr += perr; s_valid += valid;

        float g = gtA[j];
        float trust = (g > 2.f) ? cfA[j] * ocA[j] : 0.f;
        s_gtn += trust * fabsf(dcen - g);
        s_trust += trust;

        if (gx < WW - 1) {
            float ddx = fabsf(dS[ty + 1][lx0 + j + 2] - dcen);
            s_sx += ddx * __expf(-sidx[j] * (1.f / 3.f));
        }
        if (gy < HH - 1) {
            float ddy = fabsf(dS[ty + 2][lx0 + j + 1] - dcen);
            s_sy += ddy * __expf(-sidy[j] * (1.f / 3.f));
        }

        float ncv = ncP[j >> 1];
        if (ncv > 0.3f) {
            float ndv = ndP[j >> 1];
            s_act += 1.f;
            float s = (ndv > 0.f) ? 1.f : ((ndv < 0.f) ? -1.f : 0.f);
            s_sign += fmaxf(-dcen * s, 0.f);
            s_mag += ncv * fabsf(dcen - ndv);
        }
    }

    __syncthreads();
    float v;
    v = blockReduceSum(s_gtn, sbuf);   if (tid == 0) atomicAdd(&g_acc[0 * 16], (double)v);
    v = blockReduceSum(s_trust, sbuf); if (tid == 0) atomicAdd(&g_acc[1 * 16], (double)v);
    v = blockReduceSum(s_perr, sbuf);  if (tid == 0) atomicAdd(&g_acc[2 * 16], (double)v);
    v = blockReduceSum(s_valid, sbuf); if (tid == 0) atomicAdd(&g_acc[3 * 16], (double)v);
    v = blockReduceSum(s_sign, sbuf);  if (tid == 0) atomicAdd(&g_acc[4 * 16], (double)v);
    v = blockReduceSum(s_mag, sbuf);   if (tid == 0) atomicAdd(&g_acc[5 * 16], (double)v);
    v = blockReduceSum(s_act, sbuf);   if (tid == 0) atomicAdd(&g_acc[6 * 16], (double)v);
    v = blockReduceSum(s_sx, sbuf);    if (tid == 0) atomicAdd(&g_acc[7 * 16], (double)v);
    v = blockReduceSum(s_sy, sbuf);    if (tid == 0) atomicAdd(&g_acc[8 * 16], (double)v);

    // --- finalize (last block) ---
    if (tid == 0) {
        __threadfence();
        int c = atomicAdd(&g_counter, 1);
        lastFlag = (c == TILE_BLOCKS - 1) ? 1 : 0;
    }
    __syncthreads();
    if (lastFlag && tid == 0) {
        __threadfence();
        double gtl = g_acc[0 * 16] / fmax(g_acc[1 * 16], 1.0);
        double photo = g_acc[2 * 16] / fmax(g_acc[3 * 16], 1.0);
        double n = fmax(g_acc[6 * 16], 1.0);
        double signmag = 0.3 * (g_acc[4 * 16] / n) + 0.7 * (g_acc[5 * 16] / n);
        double smooth = g_acc[7 * 16] / ((double)BB * HH * (WW - 1)) +
                        g_acc[8 * 16] / ((double)BB * (HH - 1) * WW);
        out[0] = (float)(1.0 * gtl + 1.0 * photo + 0.5 * signmag + 0.1 * smooth);
        g_counter = 0;
    }
}

// ---------------- launch ----------------
extern "C" void kernel_launch(void* const* d_in, const int* in_sizes, int n_in,
                              void* d_out, int out_size) {
    const float* pred  = (const float*)d_in[0];
    const float* gt    = (const float*)d_in[1];
    const float* conf  = (const float*)d_in[2];
    const float* occ   = (const float*)d_in[3];
    const float* left  = (const float*)d_in[4];
    const float* right = (const float*)d_in[5];
    float* out = (float*)d_out;

    downsample_kernel<<<(BB * H2 * (W2 / 2) + 255) / 256, 256>>>(left, right);
    ncc_kernel<<<BB * (H2 / 4), 480>>>();
    dim3 tb(16, 8), tg(WW / 64, HH / 8, BB);
    tile_kernel<<<tg, tb>>>(pred, gt, conf, occ, left, right, out);
}

// round 9
// speedup vs baseline: 1.7727x; 1.7727x over previous
#include <cuda_runtime.h>
#include <math.h>

#define BB 4
#define HH 544
#define WW 960
#define H2 272
#define W2 480
#define MD 24
#define TILE_BLOCKS 4080

// ---------------- scratch (no allocations allowed) ----------------
__device__ float g_lg[BB * H2 * W2];
__device__ float g_rg[BB * H2 * W2];
__device__ float g_nd[BB * H2 * W2];
__device__ float g_nc[BB * H2 * W2];
// accumulators padded to one 128B line each to avoid LTS atomic serialization
// idx: 0 gtNum 1 gtDen 2 photoNum 3 photoDen 4 signSum 5 magSum 6 activeSum 7 smx 8 smy
__device__ double g_acc[9 * 16];
__device__ int g_counter;   // zero-initialized; self-resetting

// ---------------- helpers ----------------
__device__ __forceinline__ float blockReduceSum(float v, float* sbuf) {
    int tid = threadIdx.x + threadIdx.y * blockDim.x;
    int lane = tid & 31, wid = tid >> 5;
#pragma unroll
    for (int o = 16; o > 0; o >>= 1) v += __shfl_down_sync(0xffffffffu, v, o);
    if (lane == 0) sbuf[wid] = v;
    __syncthreads();
    int nw = (blockDim.x * blockDim.y + 31) >> 5;
    v = (tid < nw) ? sbuf[tid] : 0.f;
    if (wid == 0) {
#pragma unroll
        for (int o = 16; o > 0; o >>= 1) v += __shfl_down_sync(0xffffffffu, v, o);
    }
    __syncthreads();
    return v;  // valid at tid 0
}

// ---------------- kernels ----------------
// half-res grayscale + accumulator/counter zeroing (block 0)
__global__ void downsample_kernel(const float* __restrict__ left,
                                  const float* __restrict__ right) {
    if (blockIdx.x == 0) {
        if (threadIdx.x < 9 * 16) g_acc[threadIdx.x] = 0.0;
        if (threadIdx.x == 0) g_counter = 0;
    }
    int i = blockIdx.x * blockDim.x + threadIdx.x;
    const int NPAIR = W2 / 2;  // 240
    if (i >= BB * H2 * NPAIR) return;
    int px = i % NPAIR;
    int y = (i / NPAIR) % H2;
    int b = i / (NPAIR * H2);
    float l0 = 0.f, l1 = 0.f, r0 = 0.f, r1 = 0.f;
#pragma unroll
    for (int c = 0; c < 3; c++) {
        int base = ((b * 3 + c) * HH + 2 * y) * WW + 4 * px;
        float4 a0 = *(const float4*)(left + base);
        float4 a1 = *(const float4*)(left + base + WW);
        l0 += (a0.x + a0.y + a1.x + a1.y);
        l1 += (a0.z + a0.w + a1.z + a1.w);
        float4 b0 = *(const float4*)(right + base);
        float4 b1 = *(const float4*)(right + base + WW);
        r0 += (b0.x + b0.y + b1.x + b1.y);
        r1 += (b0.z + b0.w + b1.z + b1.w);
    }
    const float S = 0.25f / 3.0f;
    int o = (b * H2 + y) * W2 + 2 * px;
    *(float2*)(g_lg + o) = make_float2(l0 * S, l1 * S);
    *(float2*)(g_rg + o) = make_float2(r0 * S, r1 * S);
}

// NCC disparity search: one CTA per (b, PAIR of half-res rows), 480 threads
// (one per column). Row y0+1 stats derived from row y0 by register rolling.
// Division-free argmax: track (bestNum, bestDen), compare num*bestDen > bestNum*den.
__global__ void __launch_bounds__(480, 2) ncc_kernel() {
    __shared__ float rgS[12][528];                        // rows y0-5..y0+6, zero-padded +/-24
    __shared__ float crp0[560], cr2p0[560];               // rg column sums row0 window (idx=x+40)
    __shared__ float crp1[560], cr2p1[560];               // rg column sums row1 window
    __shared__ float Hcr0[528], Hcr20[528];               // 11-box of crp0 at u=idx-24
    __shared__ float Hcr1[528], Hcr21[528];               // 11-box of crp1
    __shared__ float ccS[2][6][496];                      // cross column sums, idx = x+8
    float* clp0 = &ccS[0][0][0];                          // setup-only aliases (560 each)
    float* cl2p0 = clp0 + 560;
    float* clp1 = clp0 + 1120;
    float* cl2p1 = clp0 + 1680;
    const float NORM = 1.0f / 121.0f;

    int pr = blockIdx.x;
    int b = pr / (H2 / 2);
    int yp = pr - b * (H2 / 2);
    int y0 = 2 * yp;
    int x = threadIdx.x;
    const float* lgB = g_lg + b * H2 * W2;
    const float* rgB = g_rg + b * H2 * W2;

    float lgR[12];
    float cr0 = 0.f, cr20 = 0.f, cl0 = 0.f, cl20 = 0.f;
    float rv0 = 0.f, rv11 = 0.f;
#pragma unroll
    for (int r = 0; r < 12; r++) {
        int yy = y0 + r - 5;
        float lv = 0.f, rv = 0.f;
        if (yy >= 0 && yy < H2) { lv = lgB[yy * W2 + x]; rv = rgB[yy * W2 + x]; }
        lgR[r] = lv;
        rgS[r][x + 24] = rv;
        if (x < 24) { rgS[r][x] = 0.f; rgS[r][x + 504] = 0.f; }
        if (r < 11) { cr0 += rv; cr20 += rv * rv; cl0 += lv; cl20 += lv * lv; }
        if (r == 0) rv0 = rv;
        if (r == 11) rv11 = rv;
    }
    float cr1 = cr0 - rv0 + rv11;
    float cr21 = cr20 - rv0 * rv0 + rv11 * rv11;
    float cl1 = cl0 - lgR[0] + lgR[11];
    float cl21 = cl20 - lgR[0] * lgR[0] + lgR[11] * lgR[11];

    crp0[x + 40] = cr0; cr2p0[x + 40] = cr20;
    crp1[x + 40] = cr1; cr2p1[x + 40] = cr21;
    clp0[x + 40] = cl0; cl2p0[x + 40] = cl20;
    clp1[x + 40] = cl1; cl2p1[x + 40] = cl21;
    if (x < 40) {
        crp0[x] = 0.f; cr2p0[x] = 0.f; crp1[x] = 0.f; cr2p1[x] = 0.f;
        clp0[x] = 0.f; cl2p0[x] = 0.f; clp1[x] = 0.f; cl2p1[x] = 0.f;
    }
    if (x >= 440) {
        crp0[x + 80] = 0.f; cr2p0[x + 80] = 0.f; crp1[x + 80] = 0.f; cr2p1[x + 80] = 0.f;
        clp0[x + 80] = 0.f; cl2p0[x + 80] = 0.f; clp1[x + 80] = 0.f; cl2p1[x + 80] = 0.f;
    }
    __syncthreads();

    // Hcr[i] = 11-box of cr centered at col i-24 : taps crp[i+11..i+21]
    for (int i = x; i < 528; i += 480) {
        float s0 = 0.f, s20 = 0.f, s1 = 0.f, s21 = 0.f;
#pragma unroll
        for (int k = 0; k < 11; k++) {
            s0 += crp0[i + 11 + k]; s20 += cr2p0[i + 11 + k];
            s1 += crp1[i + 11 + k]; s21 += cr2p1[i + 11 + k];
        }
        Hcr0[i] = s0; Hcr20[i] = s20; Hcr1[i] = s1; Hcr21[i] = s21;
    }
    // left stats for both rows
    float lm0 = 0.f, lq0 = 0.f, lm1 = 0.f, lq1 = 0.f;
#pragma unroll
    for (int k = 0; k < 11; k++) {
        lm0 += clp0[x + 35 + k]; lq0 += cl2p0[x + 35 + k];
        lm1 += clp1[x + 35 + k]; lq1 += cl2p1[x + 35 + k];
    }
    lm0 *= NORM; lq0 *= NORM; lm1 *= NORM; lq1 *= NORM;
    float ls0 = sqrtf(fmaxf(lq0 - lm0 * lm0, 1e-8f));
    float ls1 = sqrtf(fmaxf(lq1 - lm1 * lm1, 1e-8f));
    __syncthreads();   // clp reads done; ccS region now free

    // zero ccS pads (idx 0..7, 488..495) — disjoint from data writes below
    if (x < 8) {
#pragma unroll
        for (int rr = 0; rr < 2; rr++)
#pragma unroll
            for (int j = 0; j < 6; j++) { ccS[rr][j][x] = 0.f; ccS[rr][j][488 + x] = 0.f; }
    }

    // division-free argmax state: best = bestNum/bestDen, bestDen > 0 always
    float bestN0 = -1.f, bestDen0 = 1.f, bestD0 = 0.f;
    float bestN1 = -1.f, bestDen1 = 1.f, bestD1 = 0.f;
    bool interior = (x >= 5 && x < 475);
    for (int g = 0; g < 8; g++) {
        float cc0r[6], cc1r[6];
#pragma unroll
        for (int j = 0; j < 6; j++) {
            int idx = g * 6 + j;
            int d = (idx < 24) ? (idx - 24) : (idx - 23);
            int u = x + d + 24;
            float w0v = rgS[0][u];
            float s = lgR[0] * w0v;
#pragma unroll
            for (int r = 1; r < 11; r++) s += lgR[r] * rgS[r][u];
            cc0r[j] = s;
            float w11v = rgS[11][u];
            cc1r[j] = s - lgR[0] * w0v + lgR[11] * w11v;
            ccS[0][j][x + 8] = s;
            ccS[1][j][x + 8] = cc1r[j];
        }
        __syncthreads();
#pragma unroll
        for (int j = 0; j < 6; j++) {
            int idx = g * 6 + j;
            int d = (idx < 24) ? (idx - 24) : (idx - 23);
            // cross boxes: own column kept in register (10 taps each)
            float cross0 = cc0r[j], cross1 = cc1r[j];
#pragma unroll
            for (int k = -5; k < 0; k++) { cross0 += ccS[0][j][x + 8 + k]; cross1 += ccS[1][j][x + 8 + k]; }
#pragma unroll
            for (int k = 1; k <= 5; k++) { cross0 += ccS[0][j][x + 8 + k]; cross1 += ccS[1][j][x + 8 + k]; }
            float rm0_, r20_, rm1_, r21_;
            if (interior) {
                int u = x + d + 24;
                rm0_ = Hcr0[u]; r20_ = Hcr20[u]; rm1_ = Hcr1[u]; r21_ = Hcr21[u];
            } else {
                rm0_ = 0.f; r20_ = 0.f; rm1_ = 0.f; r21_ = 0.f;
#pragma unroll
                for (int k = -5; k <= 5; k++) {
                    int uu = x + k;
                    if (uu >= 0 && uu < W2) {
                        rm0_ += crp0[uu + d + 40]; r20_ += cr2p0[uu + d + 40];
                        rm1_ += crp1[uu + d + 40]; r21_ += cr2p1[uu + d + 40];
                    }
                }
            }
            float rm = rm0_ * NORM;
            float rstd = sqrtf(fmaxf(r20_ * NORM - rm * rm, 1e-8f));
            float num = cross0 * NORM - lm0 * rm;
            float den = ls0 * rstd + 1e-8f;
            if (num * bestDen0 > bestN0 * den) { bestN0 = num; bestDen0 = den; bestD0 = (float)d; }
            rm = rm1_ * NORM;
            rstd = sqrtf(fmaxf(r21_ * NORM - rm * rm, 1e-8f));
            num = cross1 * NORM - lm1 * rm;
            den = ls1 * rstd + 1e-8f;
            if (num * bestDen1 > bestN1 * den) { bestN1 = num; bestDen1 = den; bestD1 = (float)d; }
        }
        __syncthreads();
    }
    int o = (b * H2 + y0) * W2 + x;
    g_nd[o] = bestD0 * 2.0f;
    g_nc[o] = fmaxf(bestN0 / bestDen0, 0.f);
    g_nd[o + W2] = bestD1 * 2.0f;
    g_nc[o + W2] = fmaxf(bestN1 / bestDen1, 0.f);
}

// ONE fused full-res pass: warp-on-the-fly + SSIM/L1 photometric + GT anchor
// + smoothness + sign/magnitude. 64x8 tiles, 128 threads, 4 outputs/thread.
// Last block folds the finalize step.
__global__ __launch_bounds__(128) void tile_kernel(const float* __restrict__ pred,
                                                   const float* __restrict__ gt,
                                                   const float* __restrict__ conf,
                                                   const float* __restrict__ occ,
                                                   const float* __restrict__ left,
                                                   const float* __restrict__ right,
                                                   float* __restrict__ out) {
    __shared__ float lS[3][10][66];
    __shared__ float wS[3][10][66];
    __shared__ float dS[10][66];
    __shared__ float sbuf[8];
    __shared__ int lastFlag;
    int b = blockIdx.z;
    int tx0 = blockIdx.x * 64, ty0 = blockIdx.y * 8;
    int tid = threadIdx.y * 16 + threadIdx.x;

    // halo load: compute warped right on the fly
    for (int i = tid; i < 10 * 66; i += 128) {
        int col = i % 66;
        int rrow = i / 66;
        int gx = tx0 + col - 1, gy = ty0 + rrow - 1;
        if (gx >= 0 && gx < WW && gy >= 0 && gy < HH) {
            float disp = pred[(b * HH + gy) * WW + gx];
            dS[rrow][col] = disp;
            float xs = (float)gx - disp;
            float xc = fminf(fmaxf(xs, 0.f), (float)(WW - 1));
            float x0f = floorf(xc);
            float w = xc - x0f;
            int x0i = (int)x0f;
            int x1i = min(x0i + 1, WW - 1);
#pragma unroll
            for (int c = 0; c < 3; c++) {
                const float* R = right + ((b * 3 + c) * HH + gy) * WW;
                wS[c][rrow][col] = R[x0i] * (1.f - w) + R[x1i] * w;
                lS[c][rrow][col] = left[((b * 3 + c) * HH + gy) * WW + gx];
            }
        } else {
            dS[rrow][col] = 0.f;
#pragma unroll
            for (int c = 0; c < 3; c++) { wS[c][rrow][col] = 0.f; lS[c][rrow][col] = 0.f; }
        }
    }
    __syncthreads();

    int tx = threadIdx.x, ty = threadIdx.y;
    int lx0 = 4 * tx;                 // local col of first output
    int gx0 = tx0 + lx0, gy = ty0 + ty;

    float ssAcc[4] = {0, 0, 0, 0}, l1Acc[4] = {0, 0, 0, 0};
    float sidx[4] = {0, 0, 0, 0}, sidy[4] = {0, 0, 0, 0};
    const float N9 = 1.f / 9.f;
    const float C1 = 1e-4f, C2 = 9e-4f;
#pragma unroll
    for (int c = 0; c < 3; c++) {
        float win[4][5];
#pragma unroll
        for (int j = 0; j < 4; j++)
#pragma unroll
            for (int q = 0; q < 5; q++) win[j][q] = 0.f;
        float prev1 = 0.f;
#pragma unroll
        for (int u = 0; u < 6; u++) {
            float l0 = lS[c][ty][lx0 + u], l1 = lS[c][ty + 1][lx0 + u], l2 = lS[c][ty + 2][lx0 + u];
            float m0 = wS[c][ty][lx0 + u], m1 = wS[c][ty + 1][lx0 + u], m2 = wS[c][ty + 2][lx0 + u];
            float cA = l0 + l1 + l2;
            float cB = m0 + m1 + m2;
            float cC = l0 * l0 + l1 * l1 + l2 * l2;
            float cD = m0 * m0 + m1 * m1 + m2 * m2;
            float cE = l0 * m0 + l1 * m1 + l2 * m2;
#pragma unroll
            for (int j = 0; j < 4; j++) {
                if (u >= j && u <= j + 2) {
                    win[j][0] += cA; win[j][1] += cB; win[j][2] += cC;
                    win[j][3] += cD; win[j][4] += cE;
                }
            }
            if (u >= 1 && u <= 4) {
                l1Acc[u - 1] += fabsf(l1 - m1);
                sidy[u - 1] += fabsf(l2 - l1);
            }
            if (u >= 2) sidx[u - 2] += fabsf(l1 - prev1);
            prev1 = l1;
        }
#pragma unroll
        for (int j = 0; j < 4; j++) {
            float mx = win[j][0] * N9, my = win[j][1] * N9;
            float vx = fmaxf(win[j][2] * N9 - mx * mx, 0.f);
            float vy = fmaxf(win[j][3] * N9 - my * my, 0.f);
            float cxy = win[j][4] * N9 - mx * my;
            float nn = (2.f * mx * my + C1) * (2.f * cxy + C2);
            float dd = (mx * mx + my * my + C1) * (vx + vy + C2);
            ssAcc[j] += fminf(fmaxf((1.f - nn / dd) * 0.5f, 0.f), 1.f);
        }
    }

    // per-output remaining terms
    int gi0 = (b * HH + gy) * WW + gx0;
    float4 gtv = *(const float4*)(gt + gi0);
    float4 cfv = *(const float4*)(conf + gi0);
    float4 ocv = *(const float4*)(occ + gi0);
    float gtA[4] = {gtv.x, gtv.y, gtv.z, gtv.w};
    float cfA[4] = {cfv.x, cfv.y, cfv.z, cfv.w};
    float ocA[4] = {ocv.x, ocv.y, ocv.z, ocv.w};
    int hid0 = (b * H2 + (gy >> 1)) * W2 + (gx0 >> 1);
    float ncP[2] = {g_nc[hid0], g_nc[hid0 + 1]};
    float ndP[2] = {g_nd[hid0], g_nd[hid0 + 1]};

    float s_gtn = 0.f, s_trust = 0.f, s_perr = 0.f, s_valid = 0.f;
    float s_sign = 0.f, s_mag = 0.f, s_act = 0.f, s_sx = 0.f, s_sy = 0.f;
#pragma unroll
    for (int j = 0; j < 4; j++) {
        int gx = gx0 + j;
        float dcen = dS[ty + 1][lx0 + j + 1];
        float xs = (float)gx - dcen;
        float valid = (xs > 0.f && xs < (float)(WW - 1)) ? 1.f : 0.f;
        float perr = (0.85f * (ssAcc[j] * (1.f / 3.f)) + 0.15f * (l1Acc[j] * (1.f / 3.f))) * valid;
        s_perr += perr; s_valid += valid;

        float g = gtA[j];
        float trust = (g > 2.f) ? cfA[j] * ocA[j] : 0.f;
        s_gtn += trust * fabsf(dcen - g);
        s_trust += trust;

        if (gx < WW - 1) {
            float ddx = fabsf(dS[ty + 1][lx0 + j + 2] - dcen);
            s_sx += ddx * __expf(-sidx[j] * (1.f / 3.f));
        }
        if (gy < HH - 1) {
            float ddy = fabsf(dS[ty + 2][lx0 + j + 1] - dcen);
            s_sy += ddy * __expf(-sidy[j] * (1.f / 3.f));
        }

        float ncv = ncP[j >> 1];
        if (ncv > 0.3f) {
            float ndv = ndP[j >> 1];
            s_act += 1.f;
            float s = (ndv > 0.f) ? 1.f : ((ndv < 0.f) ? -1.f : 0.f);
            s_sign += fmaxf(-dcen * s, 0.f);
            s_mag += ncv * fabsf(dcen - ndv);
        }
    }

    __syncthreads();
    float v;
    v = blockReduceSum(s_gtn, sbuf);   if (tid == 0) atomicAdd(&g_acc[0 * 16], (double)v);
    v = blockReduceSum(s_trust, sbuf); if (tid == 0) atomicAdd(&g_acc[1 * 16], (double)v);
    v = blockReduceSum(s_perr, sbuf);  if (tid == 0) atomicAdd(&g_acc[2 * 16], (double)v);
    v = blockReduceSum(s_valid, sbuf); if (tid == 0) atomicAdd(&g_acc[3 * 16], (double)v);
    v = blockReduceSum(s_sign, sbuf);  if (tid == 0) atomicAdd(&g_acc[4 * 16], (double)v);
    v = blockReduceSum(s_mag, sbuf);   if (tid == 0) atomicAdd(&g_acc[5 * 16], (double)v);
    v = blockReduceSum(s_act, sbuf);   if (tid == 0) atomicAdd(&g_acc[6 * 16], (double)v);
    v = blockReduceSum(s_sx, sbuf);    if (tid == 0) atomicAdd(&g_acc[7 * 16], (double)v);
    v = blockReduceSum(s_sy, sbuf);    if (tid == 0) atomicAdd(&g_acc[8 * 16], (double)v);

    // --- finalize (last block) ---
    if (tid == 0) {
        __threadfence();
        int c = atomicAdd(&g_counter, 1);
        lastFlag = (c == TILE_BLOCKS - 1) ? 1 : 0;
    }
    __syncthreads();
    if (lastFlag && tid == 0) {
        __threadfence();
        double gtl = g_acc[0 * 16] / fmax(g_acc[1 * 16], 1.0);
        double photo = g_acc[2 * 16] / fmax(g_acc[3 * 16], 1.0);
        double n = fmax(g_acc[6 * 16], 1.0);
        double signmag = 0.3 * (g_acc[4 * 16] / n) + 0.7 * (g_acc[5 * 16] / n);
        double smooth = g_acc[7 * 16] / ((double)BB * HH * (WW - 1)) +
                        g_acc[8 * 16] / ((double)BB * (HH - 1) * WW);
        out[0] = (float)(1.0 * gtl + 1.0 * photo + 0.5 * signmag + 0.1 * smooth);
        g_counter = 0;
    }
}

// ---------------- launch ----------------
extern "C" void kernel_launch(void* const* d_in, const int* in_sizes, int n_in,
                              void* d_out, int out_size) {
    const float* pred  = (const float*)d_in[0];
    const float* gt    = (const float*)d_in[1];
    const float* conf  = (const float*)d_in[2];
    const float* occ   = (const float*)d_in[3];
    const float* left  = (const float*)d_in[4];
    const float* right = (const float*)d_in[5];
    float* out = (float*)d_out;

    downsample_kernel<<<(BB * H2 * (W2 / 2) + 255) / 256, 256>>>(left, right);
    ncc_kernel<<<BB * (H2 / 2), 480>>>();
    dim3 tb(16, 8), tg(WW / 64, HH / 8, BB);
    tile_kernel<<<tg, tb>>>(pred, gt, conf, occ, left, right, out);
}